// round 3
// baseline (speedup 1.0000x reference)
#include <cuda_runtime.h>
#include <stdint.h>
#include <math.h>

#define B_ 8
#define C_ 512
#define H_ 48
#define W_ 192
#define NTOK (B_*H_*W_)   /* 73728 tokens */

// ---------------------------------------------------------------------------
// Scratch (static device globals; no allocations anywhere).
// Q/K/V/ctx alias quarters of g_h (never live simultaneously with MLP hidden):
//   timeline: LN1 -> QKV(writes q,k,v) -> attn(writes ctx) -> outproj(reads ctx)
//             ... -> LN3(writes g_ln) -> FC1(reads g_ln, writes g_h) -> FC2.
// Total static footprint: 4 * NTOK * C_ + ... = ~1.06 GB.
// ---------------------------------------------------------------------------
__device__ float g_bufA[(size_t)NTOK * C_];      // residual stream, layout (B,W,H,C)
__device__ float g_bufB[(size_t)NTOK * C_];      // residual stream, layout (B,H,W,C)
__device__ float g_ln  [(size_t)NTOK * C_];      // layernorm output
__device__ float g_h   [(size_t)NTOK * 4 * C_];  // MLP hidden; quarters = Q,K,V,ctx

// ---------------------------------------------------------------------------
// Helpers
// ---------------------------------------------------------------------------
__device__ __forceinline__ float f2tf32(float x) {
    float r;
    asm("cvt.rna.tf32.f32 %0, %1;" : "=f"(r) : "f"(x));
    return r;
}

__device__ __forceinline__ float warp_sum(float v) {
    #pragma unroll
    for (int o = 16; o; o >>= 1) v += __shfl_xor_sync(0xffffffffu, v, o);
    return v;
}
__device__ __forceinline__ float warp_max(float v) {
    #pragma unroll
    for (int o = 16; o; o >>= 1) v = fmaxf(v, __shfl_xor_sync(0xffffffffu, v, o));
    return v;
}

#define MMA_TF32(c, a, b)                                                         \
    asm volatile("mma.sync.aligned.m16n8k8.row.col.f32.tf32.tf32.f32 "           \
                 "{%0,%1,%2,%3},{%4,%5,%6,%7},{%8,%9},{%0,%1,%2,%3};\n"          \
                 : "+f"((c)[0]), "+f"((c)[1]), "+f"((c)[2]), "+f"((c)[3])        \
                 : "r"((a)[0]), "r"((a)[1]), "r"((a)[2]), "r"((a)[3]),           \
                   "r"((b)[0]), "r"((b)[1]))

// ---------------------------------------------------------------------------
// Transposes / permutes
// ---------------------------------------------------------------------------
// (B,C,H,W) -> (B,W,H,C)
__global__ void transpose_in_kernel(const float* __restrict__ in, float* __restrict__ out) {
    __shared__ float tile[32][33];
    int bh = blockIdx.z; int b = bh / H_; int h = bh % H_;
    int w0 = blockIdx.x * 32, c0 = blockIdx.y * 32;
    int tx = threadIdx.x, ty = threadIdx.y;
    #pragma unroll
    for (int j = 0; j < 4; j++) {
        int c = c0 + ty + j * 8;
        tile[ty + j * 8][tx] = in[((size_t)(b * C_ + c) * H_ + h) * W_ + w0 + tx];
    }
    __syncthreads();
    #pragma unroll
    for (int j = 0; j < 4; j++) {
        int w = w0 + ty + j * 8;
        out[((size_t)(b * W_ + w) * H_ + h) * C_ + c0 + tx] = tile[tx][ty + j * 8];
    }
}

// (B,H,W,C) -> (B,C,H,W)
__global__ void transpose_out_kernel(const float* __restrict__ in, float* __restrict__ out) {
    __shared__ float tile[32][33];
    int bh = blockIdx.z; int b = bh / H_; int h = bh % H_;
    int w0 = blockIdx.x * 32, c0 = blockIdx.y * 32;
    int tx = threadIdx.x, ty = threadIdx.y;
    #pragma unroll
    for (int j = 0; j < 4; j++) {
        int w = w0 + ty + j * 8;
        tile[ty + j * 8][tx] = in[((size_t)((b * H_ + h) * W_ + w)) * C_ + c0 + tx];
    }
    __syncthreads();
    #pragma unroll
    for (int j = 0; j < 4; j++) {
        int c = c0 + ty + j * 8;
        out[((size_t)(b * C_ + c) * H_ + h) * W_ + w0 + tx] = tile[tx][ty + j * 8];
    }
}

// (B,W,H,C) -> (B,H,W,C); one block per output token, 128 threads copy 512 floats
__global__ void permute_mid_kernel(const float* __restrict__ in, float* __restrict__ out) {
    int t = blockIdx.x;               // output token index in (B,H,W) order
    int w = t % W_;
    int h = (t / W_) % H_;
    int b = t / (W_ * H_);
    int tin = (b * W_ + w) * H_ + h;
    const float4* src = (const float4*)(in + (size_t)tin * C_);
    float4* dst = (float4*)(out + (size_t)t * C_);
    dst[threadIdx.x] = src[threadIdx.x];
}

// ---------------------------------------------------------------------------
// LayerNorm: one warp per token (C = 512 -> 16 floats/lane as 4 float4)
// ---------------------------------------------------------------------------
__global__ void ln_kernel(const float* __restrict__ x, const float* __restrict__ g,
                          const float* __restrict__ b, float* __restrict__ y) {
    int warp = blockIdx.x * (blockDim.x >> 5) + (threadIdx.x >> 5);
    int lane = threadIdx.x & 31;
    const float4* xr = (const float4*)(x + (size_t)warp * C_);
    float4 v[4];
    float s = 0.f, s2 = 0.f;
    #pragma unroll
    for (int i = 0; i < 4; i++) {
        v[i] = xr[lane + 32 * i];
        s  += v[i].x + v[i].y + v[i].z + v[i].w;
        s2 += v[i].x * v[i].x + v[i].y * v[i].y + v[i].z * v[i].z + v[i].w * v[i].w;
    }
    s = warp_sum(s); s2 = warp_sum(s2);
    float m   = s * (1.f / C_);
    float var = s2 * (1.f / C_) - m * m;
    float rs  = rsqrtf(var + 1e-5f);
    const float4* gr = (const float4*)g;
    const float4* br = (const float4*)b;
    float4* yr = (float4*)(y + (size_t)warp * C_);
    #pragma unroll
    for (int i = 0; i < 4; i++) {
        float4 gg = gr[lane + 32 * i], bb = br[lane + 32 * i], vv = v[i], o4;
        o4.x = (vv.x - m) * rs * gg.x + bb.x;
        o4.y = (vv.y - m) * rs * gg.y + bb.y;
        o4.z = (vv.z - m) * rs * gg.z + bb.z;
        o4.w = (vv.w - m) * rs * gg.w + bb.w;
        yr[lane + 32 * i] = o4;
    }
}

// ---------------------------------------------------------------------------
// tf32 GEMM: C[M,N] = A[M,K] @ B[N,K]^T   (both K-major), M,N mult of 128, K of 32
// Block 128x128x32, 8 warps (4x2), warp tile 32x64, mma m16n8k8.
// EPI: 1 = de-interleave QKV (N=1536 -> Q/K/V [*,512])
//      2 = out = Res + acc
//      3 = out = relu(acc + Bias)
//      4 = out = Res + acc + Bias
// ---------------------------------------------------------------------------
template <int EPI>
__device__ __forceinline__ void epi_store2(float* O0, float* O1, float* O2,
                                           const float* Res, const float* Bias,
                                           int Ndim, int row, int col,
                                           float v0, float v1) {
    if (EPI == 1) {
        int gA = col, gB = col + 1;
        int cA = gA / 3, jA = gA - cA * 3;
        int cB = gB / 3, jB = gB - cB * 3;
        float* pA = (jA == 0) ? O0 : ((jA == 1) ? O1 : O2);
        float* pB = (jB == 0) ? O0 : ((jB == 1) ? O1 : O2);
        pA[(size_t)row * C_ + cA] = v0;
        pB[(size_t)row * C_ + cB] = v1;
    } else {
        size_t idx = (size_t)row * Ndim + col;
        if (EPI == 2) {
            float2 rr = *(const float2*)(Res + idx);
            v0 += rr.x; v1 += rr.y;
        } else if (EPI == 3) {
            v0 = fmaxf(v0 + Bias[col], 0.f);
            v1 = fmaxf(v1 + Bias[col + 1], 0.f);
        } else if (EPI == 4) {
            float2 rr = *(const float2*)(Res + idx);
            v0 += rr.x + Bias[col];
            v1 += rr.y + Bias[col + 1];
        }
        *(float2*)(O0 + idx) = make_float2(v0, v1);
    }
}

template <int EPI>
__global__ void __launch_bounds__(256, 2) gemm_tf32(
    const float* __restrict__ A, const float* __restrict__ Bm,
    float* __restrict__ O0, float* __restrict__ O1, float* __restrict__ O2,
    const float* __restrict__ Res, const float* __restrict__ Bias,
    int Ndim, int Kdim) {
    __shared__ float As[128][36];   // [m][k], pad 4 -> frag LDS bank-conflict-free
    __shared__ float Bs[128][36];   // [n][k]

    const int tid  = threadIdx.x;
    const int lane = tid & 31, warp = tid >> 5;
    const int wm = (warp & 3) * 32;
    const int wn = (warp >> 2) * 64;
    const int r  = lane >> 2, tc = lane & 3;
    const int mBase = blockIdx.y * 128;
    const int nBase = blockIdx.x * 128;
    const int lrow = tid >> 3;          // 0..31
    const int lc4  = (tid & 7) << 2;    // 0,4,..,28

    float acc[2][8][4];
    #pragma unroll
    for (int i = 0; i < 2; i++)
        #pragma unroll
        for (int j = 0; j < 8; j++)
            #pragma unroll
            for (int q = 0; q < 4; q++) acc[i][j][q] = 0.f;

    const int nkt = Kdim >> 5;
    for (int kt = 0; kt < nkt; kt++) {
        const int kc = (kt << 5) + lc4;
        float4 ra[4], rb[4];
        #pragma unroll
        for (int i = 0; i < 4; i++) {
            ra[i] = *(const float4*)(A  + (size_t)(mBase + lrow + i * 32) * Kdim + kc);
            rb[i] = *(const float4*)(Bm + (size_t)(nBase + lrow + i * 32) * Kdim + kc);
        }
        #pragma unroll
        for (int i = 0; i < 4; i++) {
            As[lrow + i * 32][lc4 + 0] = f2tf32(ra[i].x);
            As[lrow + i * 32][lc4 + 1] = f2tf32(ra[i].y);
            As[lrow + i * 32][lc4 + 2] = f2tf32(ra[i].z);
            As[lrow + i * 32][lc4 + 3] = f2tf32(ra[i].w);
            Bs[lrow + i * 32][lc4 + 0] = f2tf32(rb[i].x);
            Bs[lrow + i * 32][lc4 + 1] = f2tf32(rb[i].y);
            Bs[lrow + i * 32][lc4 + 2] = f2tf32(rb[i].z);
            Bs[lrow + i * 32][lc4 + 3] = f2tf32(rb[i].w);
        }
        __syncthreads();

        #pragma unroll
        for (int ks = 0; ks < 4; ks++) {
            const int k0 = ks << 3;
            uint32_t af[2][4];
            #pragma unroll
            for (int mt = 0; mt < 2; mt++) {
                const int mr = wm + mt * 16 + r;
                af[mt][0] = __float_as_uint(As[mr    ][k0 + tc]);
                af[mt][1] = __float_as_uint(As[mr + 8][k0 + tc]);
                af[mt][2] = __float_as_uint(As[mr    ][k0 + tc + 4]);
                af[mt][3] = __float_as_uint(As[mr + 8][k0 + tc + 4]);
            }
            #pragma unroll
            for (int nt = 0; nt < 8; nt++) {
                uint32_t bf[2];
                bf[0] = __float_as_uint(Bs[wn + nt * 8 + r][k0 + tc]);
                bf[1] = __float_as_uint(Bs[wn + nt * 8 + r][k0 + tc + 4]);
                #pragma unroll
                for (int mt = 0; mt < 2; mt++) {
                    MMA_TF32(acc[mt][nt], af[mt], bf);
                }
            }
        }
        __syncthreads();
    }

    // Epilogue: fragment element (row, col) mapping for m16n8k8 D
    #pragma unroll
    for (int mt = 0; mt < 2; mt++) {
        #pragma unroll
        for (int nt = 0; nt < 8; nt++) {
            int grow = mBase + wm + mt * 16 + r;
            int gcol = nBase + wn + nt * 8 + (tc << 1);
            epi_store2<EPI>(O0, O1, O2, Res, Bias, Ndim, grow,     gcol, acc[mt][nt][0], acc[mt][nt][1]);
            epi_store2<EPI>(O0, O1, O2, Res, Bias, Ndim, grow + 8, gcol, acc[mt][nt][2], acc[mt][nt][3]);
        }
    }
}

// ---------------------------------------------------------------------------
// Attention core. Tokens laid out (S, L, C) contiguous. 16 warps/block, one
// query per warp (L multiple of 16). fp32 throughout.
// ---------------------------------------------------------------------------
__global__ void __launch_bounds__(512) attn_kernel(
    const float* __restrict__ Q, const float* __restrict__ K,
    const float* __restrict__ V, float* __restrict__ O, int L) {
    __shared__ float sp[16][192];
    const int warp = threadIdx.x >> 5, lane = threadIdx.x & 31;
    const int perS = L >> 4;                 // query-blocks per sequence
    const int s  = blockIdx.x / perS;
    const int ql = (blockIdx.x % perS) * 16 + warp;
    const size_t base = (size_t)s * L;
    const float scale = 0.044194173824159216f;   // 1/sqrt(512)

    float qv[16];
    const float* qrow = Q + (base + ql) * C_;
    #pragma unroll
    for (int i = 0; i < 16; i++) qv[i] = qrow[i * 32 + lane];

    for (int k = 0; k < L; k++) {
        const float* kr = K + (base + k) * C_;
        float p = 0.f;
        #pragma unroll
        for (int i = 0; i < 16; i++) p += qv[i] * kr[i * 32 + lane];
        p = warp_sum(p);
        if (lane == 0) sp[warp][k] = p * scale;
    }
    __syncwarp();

    // softmax over L (lane-strided)
    float mx = -1e30f;
    for (int k = lane; k < L; k += 32) mx = fmaxf(mx, sp[warp][k]);
    mx = warp_max(mx);
    float sum = 0.f;
    for (int k = lane; k < L; k += 32) {
        float e = __expf(sp[warp][k] - mx);
        sp[warp][k] = e;
        sum += e;
    }
    sum = warp_sum(sum);
    float inv = 1.f / sum;
    for (int k = lane; k < L; k += 32) sp[warp][k] *= inv;
    __syncwarp();

    float accv[16];
    #pragma unroll
    for (int i = 0; i < 16; i++) accv[i] = 0.f;
    for (int k = 0; k < L; k++) {
        float w = sp[warp][k];
        const float* vr = V + (base + k) * C_;
        #pragma unroll
        for (int i = 0; i < 16; i++) accv[i] += w * vr[i * 32 + lane];
    }
    float* orow = O + (base + ql) * C_;
    #pragma unroll
    for (int i = 0; i < 16; i++) orow[i * 32 + lane] = accv[i];
}

// ---------------------------------------------------------------------------
// Host launcher
// ---------------------------------------------------------------------------
extern "C" void kernel_launch(void* const* d_in, const int* in_sizes, int n_in,
                              void* d_out, int out_size) {
    const float* x      = (const float*)d_in[0];
    const float* w_qkv1 = (const float*)d_in[1];
    const float* w_out1 = (const float*)d_in[2];
    const float* w_qkv2 = (const float*)d_in[3];
    const float* w_out2 = (const float*)d_in[4];
    const float* g1v    = (const float*)d_in[5];
    const float* b1v    = (const float*)d_in[6];
    const float* g2v    = (const float*)d_in[7];
    const float* b2v    = (const float*)d_in[8];
    const float* g3v    = (const float*)d_in[9];
    const float* b3v    = (const float*)d_in[10];
    const float* w_fc1  = (const float*)d_in[11];
    const float* b_fc1  = (const float*)d_in[12];
    const float* w_fc2  = (const float*)d_in[13];
    const float* b_fc2  = (const float*)d_in[14];
    float* out = (float*)d_out;

    static float *bufA = nullptr, *bufB, *lnb, *hb;
    if (!bufA) {
        cudaGetSymbolAddress((void**)&bufA, g_bufA);
        cudaGetSymbolAddress((void**)&bufB, g_bufB);
        cudaGetSymbolAddress((void**)&lnb,  g_ln);
        cudaGetSymbolAddress((void**)&hb,   g_h);
    }
    // Q/K/V/ctx alias quarters of the 4C-wide MLP hidden buffer (disjoint lifetimes)
    float* qb   = hb;
    float* kb   = hb + (size_t)NTOK * C_;
    float* vb   = hb + (size_t)2 * NTOK * C_;
    float* ctxb = hb + (size_t)3 * NTOK * C_;

    dim3 tblk(32, 8);
    dim3 tgrid(W_ / 32, C_ / 32, B_ * H_);

    // 1. (B,C,H,W) -> (B,W,H,C)
    transpose_in_kernel<<<tgrid, tblk>>>(x, bufA);

    // 2. LN1
    ln_kernel<<<NTOK / 8, 256>>>(bufA, g1v, b1v, lnb);

    // 3. QKV1 (de-interleave into Q/K/V)
    gemm_tf32<1><<<dim3(1536 / 128, NTOK / 128), 256>>>(
        lnb, w_qkv1, qb, kb, vb, nullptr, nullptr, 1536, 512);

    // 4. attention along H: S = B*W = 1536, L = 48
    attn_kernel<<<1536 * (48 / 16), 512>>>(qb, kb, vb, ctxb, 48);

    // 5. out-proj + residual (in-place on bufA)
    gemm_tf32<2><<<dim3(512 / 128, NTOK / 128), 256>>>(
        ctxb, w_out1, bufA, nullptr, nullptr, bufA, nullptr, 512, 512);

    // 6. (B,W,H,C) -> (B,H,W,C)
    permute_mid_kernel<<<NTOK, 128>>>(bufA, bufB);

    // 7. LN2
    ln_kernel<<<NTOK / 8, 256>>>(bufB, g2v, b2v, lnb);

    // 8. QKV2
    gemm_tf32<1><<<dim3(1536 / 128, NTOK / 128), 256>>>(
        lnb, w_qkv2, qb, kb, vb, nullptr, nullptr, 1536, 512);

    // 9. attention along W: S = B*H = 384, L = 192
    attn_kernel<<<384 * (192 / 16), 512>>>(qb, kb, vb, ctxb, 192);

    // 10. out-proj + residual (in-place on bufB)
    gemm_tf32<2><<<dim3(512 / 128, NTOK / 128), 256>>>(
        ctxb, w_out2, bufB, nullptr, nullptr, bufB, nullptr, 512, 512);

    // 11. LN3
    ln_kernel<<<NTOK / 8, 256>>>(bufB, g3v, b3v, lnb);

    // 12. FC1 + bias + relu (writes g_h — Q/K/V/ctx lifetimes are over)
    gemm_tf32<3><<<dim3(2048 / 128, NTOK / 128), 256>>>(
        lnb, w_fc1, hb, nullptr, nullptr, nullptr, b_fc1, 2048, 512);

    // 13. FC2 + bias + residual
    gemm_tf32<4><<<dim3(512 / 128, NTOK / 128), 256>>>(
        hb, w_fc2, bufB, nullptr, nullptr, bufB, b_fc2, 512, 2048);

    // 14. (B,H,W,C) -> (B,C,H,W)
    transpose_out_kernel<<<tgrid, tblk>>>(bufB, out);
}

// round 5
// speedup vs baseline: 1.4893x; 1.4893x over previous
#include <cuda_runtime.h>
#include <cuda_fp16.h>
#include <stdint.h>
#include <math.h>

#define B_ 8
#define C_ 512
#define H_ 48
#define W_ 192
#define NTOK (B_*H_*W_)   /* 73728 tokens */

// ---------------------------------------------------------------------------
// Scratch (static device globals; no allocations anywhere).
// q/k/v/ctx (half) alias quarters of g_hh (disjoint lifetimes vs MLP hidden).
// ---------------------------------------------------------------------------
__device__ float  g_bufA[(size_t)NTOK * C_];      // residual, layout (B,W,H,C)
__device__ float  g_bufB[(size_t)NTOK * C_];      // residual, layout (B,H,W,C)
__device__ __half g_lnh [(size_t)NTOK * C_];      // layernorm output (half)
__device__ __half g_hh  [(size_t)NTOK * 4 * C_];  // MLP hidden; quarters = q,k,v,ctx
__device__ __half g_wq1h[3 * C_ * C_];
__device__ __half g_wo1h[C_ * C_];
__device__ __half g_wq2h[3 * C_ * C_];
__device__ __half g_wo2h[C_ * C_];
__device__ __half g_wf1h[4 * C_ * C_];
__device__ __half g_wf2h[4 * C_ * C_];

// ---------------------------------------------------------------------------
// Helpers
// ---------------------------------------------------------------------------
__device__ __forceinline__ float warp_sum(float v) {
    #pragma unroll
    for (int o = 16; o; o >>= 1) v += __shfl_xor_sync(0xffffffffu, v, o);
    return v;
}
__device__ __forceinline__ float warp_max(float v) {
    #pragma unroll
    for (int o = 16; o; o >>= 1) v = fmaxf(v, __shfl_xor_sync(0xffffffffu, v, o));
    return v;
}

#define MMA_F16(c, a, b)                                                          \
    asm volatile("mma.sync.aligned.m16n8k16.row.col.f32.f16.f16.f32 "            \
                 "{%0,%1,%2,%3},{%4,%5,%6,%7},{%8,%9},{%0,%1,%2,%3};\n"          \
                 : "+f"((c)[0]), "+f"((c)[1]), "+f"((c)[2]), "+f"((c)[3])        \
                 : "r"((a)[0]), "r"((a)[1]), "r"((a)[2]), "r"((a)[3]),           \
                   "r"((b)[0]), "r"((b)[1]))

#define CP_ASYNC16(dst_u32, src_ptr)                                              \
    asm volatile("cp.async.cg.shared.global [%0], [%1], 16;\n"                    \
                 :: "r"(dst_u32), "l"(src_ptr))
#define CP_COMMIT asm volatile("cp.async.commit_group;\n")
#define CP_WAIT1  asm volatile("cp.async.wait_group 1;\n")

// ---------------------------------------------------------------------------
// fp32 -> fp16 elementwise (weights); n4 = n/4
// ---------------------------------------------------------------------------
__global__ void f2h_kernel(const float* __restrict__ in, __half* __restrict__ out, int n4) {
    int i = blockIdx.x * 256 + threadIdx.x;
    if (i < n4) {
        float4 v = ((const float4*)in)[i];
        ((half2*)out)[2 * i]     = __floats2half2_rn(v.x, v.y);
        ((half2*)out)[2 * i + 1] = __floats2half2_rn(v.z, v.w);
    }
}

// ---------------------------------------------------------------------------
// Transposes / permutes (fp32 residual stream)
// ---------------------------------------------------------------------------
__global__ void transpose_in_kernel(const float* __restrict__ in, float* __restrict__ out) {
    __shared__ float tile[32][33];
    int bh = blockIdx.z; int b = bh / H_; int h = bh % H_;
    int w0 = blockIdx.x * 32, c0 = blockIdx.y * 32;
    int tx = threadIdx.x, ty = threadIdx.y;
    #pragma unroll
    for (int j = 0; j < 4; j++) {
        int c = c0 + ty + j * 8;
        tile[ty + j * 8][tx] = in[((size_t)(b * C_ + c) * H_ + h) * W_ + w0 + tx];
    }
    __syncthreads();
    #pragma unroll
    for (int j = 0; j < 4; j++) {
        int w = w0 + ty + j * 8;
        out[((size_t)(b * W_ + w) * H_ + h) * C_ + c0 + tx] = tile[tx][ty + j * 8];
    }
}

__global__ void transpose_out_kernel(const float* __restrict__ in, float* __restrict__ out) {
    __shared__ float tile[32][33];
    int bh = blockIdx.z; int b = bh / H_; int h = bh % H_;
    int w0 = blockIdx.x * 32, c0 = blockIdx.y * 32;
    int tx = threadIdx.x, ty = threadIdx.y;
    #pragma unroll
    for (int j = 0; j < 4; j++) {
        int w = w0 + ty + j * 8;
        tile[ty + j * 8][tx] = in[((size_t)((b * H_ + h) * W_ + w)) * C_ + c0 + tx];
    }
    __syncthreads();
    #pragma unroll
    for (int j = 0; j < 4; j++) {
        int c = c0 + ty + j * 8;
        out[((size_t)(b * C_ + c) * H_ + h) * W_ + w0 + tx] = tile[tx][ty + j * 8];
    }
}

__global__ void permute_mid_kernel(const float* __restrict__ in, float* __restrict__ out) {
    int t = blockIdx.x;               // output token index in (B,H,W) order
    int w = t % W_;
    int h = (t / W_) % H_;
    int b = t / (W_ * H_);
    int tin = (b * W_ + w) * H_ + h;
    const float4* src = (const float4*)(in + (size_t)tin * C_);
    float4* dst = (float4*)(out + (size_t)t * C_);
    dst[threadIdx.x] = src[threadIdx.x];
}

// ---------------------------------------------------------------------------
// LayerNorm: fp32 in -> half out. One warp per token.
// ---------------------------------------------------------------------------
__global__ void ln_kernel(const float* __restrict__ x, const float* __restrict__ g,
                          const float* __restrict__ b, __half* __restrict__ y) {
    int warp = blockIdx.x * (blockDim.x >> 5) + (threadIdx.x >> 5);
    int lane = threadIdx.x & 31;
    const float4* xr = (const float4*)(x + (size_t)warp * C_);
    float4 v[4];
    float s = 0.f, s2 = 0.f;
    #pragma unroll
    for (int i = 0; i < 4; i++) {
        v[i] = xr[lane + 32 * i];
        s  += v[i].x + v[i].y + v[i].z + v[i].w;
        s2 += v[i].x * v[i].x + v[i].y * v[i].y + v[i].z * v[i].z + v[i].w * v[i].w;
    }
    s = warp_sum(s); s2 = warp_sum(s2);
    float m   = s * (1.f / C_);
    float var = s2 * (1.f / C_) - m * m;
    float rs  = rsqrtf(var + 1e-5f);
    const float4* gr = (const float4*)g;
    const float4* br = (const float4*)b;
    half2* yr = (half2*)(y + (size_t)warp * C_);
    #pragma unroll
    for (int i = 0; i < 4; i++) {
        float4 gg = gr[lane + 32 * i], bb = br[lane + 32 * i], vv = v[i], o4;
        o4.x = (vv.x - m) * rs * gg.x + bb.x;
        o4.y = (vv.y - m) * rs * gg.y + bb.y;
        o4.z = (vv.z - m) * rs * gg.z + bb.z;
        o4.w = (vv.w - m) * rs * gg.w + bb.w;
        yr[2 * (lane + 32 * i)]     = __floats2half2_rn(o4.x, o4.y);
        yr[2 * (lane + 32 * i) + 1] = __floats2half2_rn(o4.z, o4.w);
    }
}

// ---------------------------------------------------------------------------
// fp16 GEMM, fp32 accum: C[M,N] = A[M,K] @ B[N,K]^T, both K-major half.
// Block 128x128, BK=32, 8 warps (4x2), warp tile 32x64, mma m16n8k16,
// cp.async double-buffered.
// EPI: 1 = de-interleave QKV -> half q/k/v
//      2 = fp32 out = Res + acc
//      3 = half out = relu(acc + Bias)
//      4 = fp32 out = Res + acc + Bias
// ---------------------------------------------------------------------------
template <int EPI>
__device__ __forceinline__ void epi_store2(void* O0v, void* O1v, void* O2v,
                                           const float* Res, const float* Bias,
                                           int Ndim, int row, int col,
                                           float v0, float v1) {
    if (EPI == 1) {
        __half* O0 = (__half*)O0v; __half* O1 = (__half*)O1v; __half* O2 = (__half*)O2v;
        int gA = col, gB = col + 1;
        int cA = gA / 3, jA = gA - cA * 3;
        int cB = gB / 3, jB = gB - cB * 3;
        __half* pA = (jA == 0) ? O0 : ((jA == 1) ? O1 : O2);
        __half* pB = (jB == 0) ? O0 : ((jB == 1) ? O1 : O2);
        pA[(size_t)row * C_ + cA] = __float2half_rn(v0);
        pB[(size_t)row * C_ + cB] = __float2half_rn(v1);
    } else {
        size_t idx = (size_t)row * Ndim + col;
        if (EPI == 3) {
            v0 = fmaxf(v0 + Bias[col], 0.f);
            v1 = fmaxf(v1 + Bias[col + 1], 0.f);
            *(half2*)((__half*)O0v + idx) = __floats2half2_rn(v0, v1);
        } else {
            float* O0 = (float*)O0v;
            float2 rr = *(const float2*)(Res + idx);
            if (EPI == 2) { v0 += rr.x; v1 += rr.y; }
            else          { v0 += rr.x + Bias[col]; v1 += rr.y + Bias[col + 1]; }
            *(float2*)(O0 + idx) = make_float2(v0, v1);
        }
    }
}

template <int EPI>
__global__ void __launch_bounds__(256, 2) gemm_f16(
    const __half* __restrict__ A, const __half* __restrict__ Bm,
    void* O0, void* O1, void* O2,
    const float* __restrict__ Res, const float* __restrict__ Bias,
    int Ndim, int Kdim) {
    // pad to 40 halves/row: LDGSTS dst 16B-aligned (80B pitch), frag LDS conflict-free
    __shared__ __half As[2][128][40];
    __shared__ __half Bs[2][128][40];

    const int tid  = threadIdx.x;
    const int lane = tid & 31, warp = tid >> 5;
    const int wm = (warp & 3) * 32;
    const int wn = (warp >> 2) * 64;
    const int r  = lane >> 2, tc = lane & 3;
    const int mBase = blockIdx.y * 128;
    const int nBase = blockIdx.x * 128;
    const int lrow = tid >> 2;          // 0..63 (rows lrow and lrow+64)
    const int lch  = (tid & 3) * 8;     // halves offset within 32-half k-slab

    float acc[2][8][4];
    #pragma unroll
    for (int i = 0; i < 2; i++)
        #pragma unroll
        for (int j = 0; j < 8; j++)
            #pragma unroll
            for (int q = 0; q < 4; q++) acc[i][j][q] = 0.f;

    const int nkt = Kdim >> 5;

    // prefetch tile 0
    {
        const __half* ga0 = A  + (size_t)(mBase + lrow) * Kdim + lch;
        const __half* ga1 = A  + (size_t)(mBase + lrow + 64) * Kdim + lch;
        const __half* gb0 = Bm + (size_t)(nBase + lrow) * Kdim + lch;
        const __half* gb1 = Bm + (size_t)(nBase + lrow + 64) * Kdim + lch;
        CP_ASYNC16((uint32_t)__cvta_generic_to_shared(&As[0][lrow][lch]), ga0);
        CP_ASYNC16((uint32_t)__cvta_generic_to_shared(&As[0][lrow + 64][lch]), ga1);
        CP_ASYNC16((uint32_t)__cvta_generic_to_shared(&Bs[0][lrow][lch]), gb0);
        CP_ASYNC16((uint32_t)__cvta_generic_to_shared(&Bs[0][lrow + 64][lch]), gb1);
    }
    CP_COMMIT;

    for (int kt = 0; kt < nkt; kt++) {
        const int cur = kt & 1;
        if (kt + 1 < nkt) {
            const int nxt = (kt + 1) & 1;
            const int kc = (kt + 1) << 5;
            const __half* ga0 = A  + (size_t)(mBase + lrow) * Kdim + kc + lch;
            const __half* ga1 = A  + (size_t)(mBase + lrow + 64) * Kdim + kc + lch;
            const __half* gb0 = Bm + (size_t)(nBase + lrow) * Kdim + kc + lch;
            const __half* gb1 = Bm + (size_t)(nBase + lrow + 64) * Kdim + kc + lch;
            CP_ASYNC16((uint32_t)__cvta_generic_to_shared(&As[nxt][lrow][lch]), ga0);
            CP_ASYNC16((uint32_t)__cvta_generic_to_shared(&As[nxt][lrow + 64][lch]), ga1);
            CP_ASYNC16((uint32_t)__cvta_generic_to_shared(&Bs[nxt][lrow][lch]), gb0);
            CP_ASYNC16((uint32_t)__cvta_generic_to_shared(&Bs[nxt][lrow + 64][lch]), gb1);
        }
        CP_COMMIT;
        CP_WAIT1;
        __syncthreads();

        #pragma unroll
        for (int ks = 0; ks < 2; ks++) {
            const int k0 = ks << 4;
            uint32_t af[2][4];
            #pragma unroll
            for (int mt = 0; mt < 2; mt++) {
                const int mr = wm + mt * 16 + r;
                af[mt][0] = *(const uint32_t*)&As[cur][mr    ][k0 + 2 * tc];
                af[mt][1] = *(const uint32_t*)&As[cur][mr + 8][k0 + 2 * tc];
                af[mt][2] = *(const uint32_t*)&As[cur][mr    ][k0 + 2 * tc + 8];
                af[mt][3] = *(const uint32_t*)&As[cur][mr + 8][k0 + 2 * tc + 8];
            }
            #pragma unroll
            for (int nt = 0; nt < 8; nt++) {
                const int nr = wn + nt * 8 + r;
                uint32_t bf[2];
                bf[0] = *(const uint32_t*)&Bs[cur][nr][k0 + 2 * tc];
                bf[1] = *(const uint32_t*)&Bs[cur][nr][k0 + 2 * tc + 8];
                #pragma unroll
                for (int mt = 0; mt < 2; mt++) {
                    MMA_F16(acc[mt][nt], af[mt], bf);
                }
            }
        }
        __syncthreads();
    }

    #pragma unroll
    for (int mt = 0; mt < 2; mt++) {
        #pragma unroll
        for (int nt = 0; nt < 8; nt++) {
            int grow = mBase + wm + mt * 16 + r;
            int gcol = nBase + wn + nt * 8 + (tc << 1);
            epi_store2<EPI>(O0, O1, O2, Res, Bias, Ndim, grow,     gcol, acc[mt][nt][0], acc[mt][nt][1]);
            epi_store2<EPI>(O0, O1, O2, Res, Bias, Ndim, grow + 8, gcol, acc[mt][nt][2], acc[mt][nt][3]);
        }
    }
}

// ---------------------------------------------------------------------------
// Attention core: half q/k/v in, fp32 math, half ctx out.
// Tokens (S, L, C) contiguous. 16 warps/block, one query per warp.
// ---------------------------------------------------------------------------
__global__ void __launch_bounds__(512) attn_kernel(
    const __half* __restrict__ Q, const __half* __restrict__ K,
    const __half* __restrict__ V, __half* __restrict__ O, int L) {
    __shared__ float sp[16][192];
    const int warp = threadIdx.x >> 5, lane = threadIdx.x & 31;
    const int perS = L >> 4;
    const int s  = blockIdx.x / perS;
    const int ql = (blockIdx.x % perS) * 16 + warp;
    const size_t base = (size_t)s * L;
    const float scale = 0.044194173824159216f;   // 1/sqrt(512)

    float2 qf[8];
    const half2* qrow = (const half2*)(Q + (base + ql) * C_);
    #pragma unroll
    for (int i = 0; i < 8; i++) qf[i] = __half22float2(qrow[i * 32 + lane]);

    for (int k = 0; k < L; k++) {
        const half2* kr = (const half2*)(K + (base + k) * C_);
        float p = 0.f;
        #pragma unroll
        for (int i = 0; i < 8; i++) {
            float2 kf = __half22float2(kr[i * 32 + lane]);
            p += qf[i].x * kf.x + qf[i].y * kf.y;
        }
        p = warp_sum(p);
        if (lane == 0) sp[warp][k] = p * scale;
    }
    __syncwarp();

    float mx = -1e30f;
    for (int k = lane; k < L; k += 32) mx = fmaxf(mx, sp[warp][k]);
    mx = warp_max(mx);
    float sum = 0.f;
    for (int k = lane; k < L; k += 32) {
        float e = __expf(sp[warp][k] - mx);
        sp[warp][k] = e;
        sum += e;
    }
    sum = warp_sum(sum);
    float inv = 1.f / sum;
    for (int k = lane; k < L; k += 32) sp[warp][k] *= inv;
    __syncwarp();

    float2 accv[8];
    #pragma unroll
    for (int i = 0; i < 8; i++) accv[i] = make_float2(0.f, 0.f);
    for (int k = 0; k < L; k++) {
        float w = sp[warp][k];
        const half2* vr = (const half2*)(V + (base + k) * C_);
        #pragma unroll
        for (int i = 0; i < 8; i++) {
            float2 vf = __half22float2(vr[i * 32 + lane]);
            accv[i].x += w * vf.x;
            accv[i].y += w * vf.y;
        }
    }
    half2* orow = (half2*)(O + (base + ql) * C_);
    #pragma unroll
    for (int i = 0; i < 8; i++) orow[i * 32 + lane] = __floats2half2_rn(accv[i].x, accv[i].y);
}

// ---------------------------------------------------------------------------
// Host launcher
// ---------------------------------------------------------------------------
extern "C" void kernel_launch(void* const* d_in, const int* in_sizes, int n_in,
                              void* d_out, int out_size) {
    const float* x      = (const float*)d_in[0];
    const float* w_qkv1 = (const float*)d_in[1];
    const float* w_out1 = (const float*)d_in[2];
    const float* w_qkv2 = (const float*)d_in[3];
    const float* w_out2 = (const float*)d_in[4];
    const float* g1v    = (const float*)d_in[5];
    const float* b1v    = (const float*)d_in[6];
    const float* g2v    = (const float*)d_in[7];
    const float* b2v    = (const float*)d_in[8];
    const float* g3v    = (const float*)d_in[9];
    const float* b3v    = (const float*)d_in[10];
    const float* w_fc1  = (const float*)d_in[11];
    const float* b_fc1  = (const float*)d_in[12];
    const float* w_fc2  = (const float*)d_in[13];
    const float* b_fc2  = (const float*)d_in[14];
    float* out = (float*)d_out;

    static float *bufA = nullptr, *bufB;
    static __half *lnh, *hh, *wq1h, *wo1h, *wq2h, *wo2h, *wf1h, *wf2h;
    if (!bufA) {
        cudaGetSymbolAddress((void**)&bufA, g_bufA);
        cudaGetSymbolAddress((void**)&bufB, g_bufB);
        cudaGetSymbolAddress((void**)&lnh,  g_lnh);
        cudaGetSymbolAddress((void**)&hh,   g_hh);
        cudaGetSymbolAddress((void**)&wq1h, g_wq1h);
        cudaGetSymbolAddress((void**)&wo1h, g_wo1h);
        cudaGetSymbolAddress((void**)&wq2h, g_wq2h);
        cudaGetSymbolAddress((void**)&wo2h, g_wo2h);
        cudaGetSymbolAddress((void**)&wf1h, g_wf1h);
        cudaGetSymbolAddress((void**)&wf2h, g_wf2h);
    }
    // q/k/v/ctx alias quarters of the 4C-wide MLP hidden buffer
    __half* qb   = hh;
    __half* kb   = hh + (size_t)NTOK * C_;
    __half* vb   = hh + (size_t)2 * NTOK * C_;
    __half* ctxb = hh + (size_t)3 * NTOK * C_;

    // weight conversions (cheap, ~4.2M elems total)
    f2h_kernel<<<(3 * C_ * C_ / 4 + 255) / 256, 256>>>(w_qkv1, wq1h, 3 * C_ * C_ / 4);
    f2h_kernel<<<(C_ * C_ / 4 + 255) / 256,     256>>>(w_out1, wo1h, C_ * C_ / 4);
    f2h_kernel<<<(3 * C_ * C_ / 4 + 255) / 256, 256>>>(w_qkv2, wq2h, 3 * C_ * C_ / 4);
    f2h_kernel<<<(C_ * C_ / 4 + 255) / 256,     256>>>(w_out2, wo2h, C_ * C_ / 4);
    f2h_kernel<<<(4 * C_ * C_ / 4 + 255) / 256, 256>>>(w_fc1,  wf1h, 4 * C_ * C_ / 4);
    f2h_kernel<<<(4 * C_ * C_ / 4 + 255) / 256, 256>>>(w_fc2,  wf2h, 4 * C_ * C_ / 4);

    dim3 tblk(32, 8);
    dim3 tgrid(W_ / 32, C_ / 32, B_ * H_);

    // 1. (B,C,H,W) -> (B,W,H,C)
    transpose_in_kernel<<<tgrid, tblk>>>(x, bufA);

    // 2. LN1 -> half
    ln_kernel<<<NTOK / 8, 256>>>(bufA, g1v, b1v, lnh);

    // 3. QKV1 (de-interleave into half q/k/v)
    gemm_f16<1><<<dim3(1536 / 128, NTOK / 128), 256>>>(
        lnh, wq1h, qb, kb, vb, nullptr, nullptr, 1536, 512);

    // 4. attention along H: S = B*W = 1536, L = 48
    attn_kernel<<<1536 * (48 / 16), 512>>>(qb, kb, vb, ctxb, 48);

    // 5. out-proj + residual (fp32, in-place on bufA)
    gemm_f16<2><<<dim3(512 / 128, NTOK / 128), 256>>>(
        ctxb, wo1h, bufA, nullptr, nullptr, bufA, nullptr, 512, 512);

    // 6. (B,W,H,C) -> (B,H,W,C)
    permute_mid_kernel<<<NTOK, 128>>>(bufA, bufB);

    // 7. LN2 -> half
    ln_kernel<<<NTOK / 8, 256>>>(bufB, g2v, b2v, lnh);

    // 8. QKV2
    gemm_f16<1><<<dim3(1536 / 128, NTOK / 128), 256>>>(
        lnh, wq2h, qb, kb, vb, nullptr, nullptr, 1536, 512);

    // 9. attention along W: S = B*H = 384, L = 192
    attn_kernel<<<384 * (192 / 16), 512>>>(qb, kb, vb, ctxb, 192);

    // 10. out-proj + residual (fp32, in-place on bufB)
    gemm_f16<2><<<dim3(512 / 128, NTOK / 128), 256>>>(
        ctxb, wo2h, bufB, nullptr, nullptr, bufB, nullptr, 512, 512);

    // 11. LN3 -> half
    ln_kernel<<<NTOK / 8, 256>>>(bufB, g3v, b3v, lnh);

    // 12. FC1 + bias + relu -> half hidden (q/k/v/ctx lifetimes over)
    gemm_f16<3><<<dim3(2048 / 128, NTOK / 128), 256>>>(
        lnh, wf1h, hh, nullptr, nullptr, nullptr, b_fc1, 2048, 512);

    // 13. FC2 + bias + residual (fp32, K=2048)
    gemm_f16<4><<<dim3(512 / 128, NTOK / 128), 256>>>(
        hh, wf2h, bufB, nullptr, nullptr, bufB, b_fc2, 512, 2048);

    // 14. (B,H,W,C) -> (B,C,H,W)
    transpose_out_kernel<<<tgrid, tblk>>>(bufB, out);
}

// round 7
// speedup vs baseline: 1.5934x; 1.0699x over previous
#include <cuda_runtime.h>
#include <cuda_fp16.h>
#include <stdint.h>
#include <math.h>

#define B_ 8
#define C_ 512
#define H_ 48
#define W_ 192
#define NTOK (B_*H_*W_)   /* 73728 tokens */

// ---------------------------------------------------------------------------
// Scratch (static device globals; no allocations anywhere).
// ---------------------------------------------------------------------------
__device__ float  g_bufA[(size_t)NTOK * C_];
__device__ float  g_bufB[(size_t)NTOK * C_];
__device__ __half g_lnh [(size_t)NTOK * C_];
__device__ __half g_hh  [(size_t)NTOK * 4 * C_];  // MLP hidden; quarters = q,k,v,ctx
__device__ __half g_wq1h[3 * C_ * C_];
__device__ __half g_wo1h[C_ * C_];
__device__ __half g_wq2h[3 * C_ * C_];
__device__ __half g_wo2h[C_ * C_];
__device__ __half g_wf1h[4 * C_ * C_];
__device__ __half g_wf2h[4 * C_ * C_];

// ---------------------------------------------------------------------------
// Helpers
// ---------------------------------------------------------------------------
__device__ __forceinline__ uint32_t smem_u32(const void* p) {
    uint32_t a;
    asm("{ .reg .u64 t; cvta.to.shared.u64 t, %1; cvt.u32.u64 %0, t; }" : "=r"(a) : "l"(p));
    return a;
}

__device__ __forceinline__ float warp_sum(float v) {
    #pragma unroll
    for (int o = 16; o; o >>= 1) v += __shfl_xor_sync(0xffffffffu, v, o);
    return v;
}
__device__ __forceinline__ float warp_max(float v) {
    #pragma unroll
    for (int o = 16; o; o >>= 1) v = fmaxf(v, __shfl_xor_sync(0xffffffffu, v, o));
    return v;
}

#define MMA_F16(c, a0, a1, a2, a3, b0, b1)                                        \
    asm volatile("mma.sync.aligned.m16n8k16.row.col.f32.f16.f16.f32 "            \
                 "{%0,%1,%2,%3},{%4,%5,%6,%7},{%8,%9},{%0,%1,%2,%3};\n"          \
                 : "+f"((c)[0]), "+f"((c)[1]), "+f"((c)[2]), "+f"((c)[3])        \
                 : "r"(a0), "r"(a1), "r"(a2), "r"(a3), "r"(b0), "r"(b1))

#define LDSM4(r0, r1, r2, r3, addr)                                               \
    asm volatile("ldmatrix.sync.aligned.m8n8.x4.shared.b16 {%0,%1,%2,%3},[%4];"  \
                 : "=r"(r0), "=r"(r1), "=r"(r2), "=r"(r3) : "r"(addr))

#define CP_ASYNC16(dst_u32, src_ptr)                                              \
    asm volatile("cp.async.cg.shared.global [%0], [%1], 16;\n"                    \
                 :: "r"(dst_u32), "l"(src_ptr))
#define CP_COMMIT asm volatile("cp.async.commit_group;\n")
#define CP_WAIT1  asm volatile("cp.async.wait_group 1;\n" ::: "memory")

// ---------------------------------------------------------------------------
// fp32 -> fp16 elementwise (weights); n4 = n/4
// ---------------------------------------------------------------------------
__global__ void f2h_kernel(const float* __restrict__ in, __half* __restrict__ out, int n4) {
    int i = blockIdx.x * 256 + threadIdx.x;
    if (i < n4) {
        float4 v = ((const float4*)in)[i];
        ((half2*)out)[2 * i]     = __floats2half2_rn(v.x, v.y);
        ((half2*)out)[2 * i + 1] = __floats2half2_rn(v.z, v.w);
    }
}

// ---------------------------------------------------------------------------
// Transposes / permutes (fp32 residual stream)
// ---------------------------------------------------------------------------
__global__ void transpose_in_kernel(const float* __restrict__ in, float* __restrict__ out) {
    __shared__ float tile[32][33];
    int bh = blockIdx.z; int b = bh / H_; int h = bh % H_;
    int w0 = blockIdx.x * 32, c0 = blockIdx.y * 32;
    int tx = threadIdx.x, ty = threadIdx.y;
    #pragma unroll
    for (int j = 0; j < 4; j++) {
        int c = c0 + ty + j * 8;
        tile[ty + j * 8][tx] = in[((size_t)(b * C_ + c) * H_ + h) * W_ + w0 + tx];
    }
    __syncthreads();
    #pragma unroll
    for (int j = 0; j < 4; j++) {
        int w = w0 + ty + j * 8;
        out[((size_t)(b * W_ + w) * H_ + h) * C_ + c0 + tx] = tile[tx][ty + j * 8];
    }
}

__global__ void transpose_out_kernel(const float* __restrict__ in, float* __restrict__ out) {
    __shared__ float tile[32][33];
    int bh = blockIdx.z; int b = bh / H_; int h = bh % H_;
    int w0 = blockIdx.x * 32, c0 = blockIdx.y * 32;
    int tx = threadIdx.x, ty = threadIdx.y;
    #pragma unroll
    for (int j = 0; j < 4; j++) {
        int w = w0 + ty + j * 8;
        tile[ty + j * 8][tx] = in[((size_t)((b * H_ + h) * W_ + w)) * C_ + c0 + tx];
    }
    __syncthreads();
    #pragma unroll
    for (int j = 0; j < 4; j++) {
        int c = c0 + ty + j * 8;
        out[((size_t)(b * C_ + c) * H_ + h) * W_ + w0 + tx] = tile[tx][ty + j * 8];
    }
}

__global__ void permute_mid_kernel(const float* __restrict__ in, float* __restrict__ out) {
    int t = blockIdx.x;
    int w = t % W_;
    int h = (t / W_) % H_;
    int b = t / (W_ * H_);
    int tin = (b * W_ + w) * H_ + h;
    const float4* src = (const float4*)(in + (size_t)tin * C_);
    float4* dst = (float4*)(out + (size_t)t * C_);
    dst[threadIdx.x] = src[threadIdx.x];
}

// ---------------------------------------------------------------------------
// LayerNorm: fp32 in -> half out. One warp per token.
// ---------------------------------------------------------------------------
__global__ void ln_kernel(const float* __restrict__ x, const float* __restrict__ g,
                          const float* __restrict__ b, __half* __restrict__ y) {
    int warp = blockIdx.x * (blockDim.x >> 5) + (threadIdx.x >> 5);
    int lane = threadIdx.x & 31;
    const float4* xr = (const float4*)(x + (size_t)warp * C_);
    float4 v[4];
    float s = 0.f, s2 = 0.f;
    #pragma unroll
    for (int i = 0; i < 4; i++) {
        v[i] = xr[lane + 32 * i];
        s  += v[i].x + v[i].y + v[i].z + v[i].w;
        s2 += v[i].x * v[i].x + v[i].y * v[i].y + v[i].z * v[i].z + v[i].w * v[i].w;
    }
    s = warp_sum(s); s2 = warp_sum(s2);
    float m   = s * (1.f / C_);
    float var = s2 * (1.f / C_) - m * m;
    float rs  = rsqrtf(var + 1e-5f);
    const float4* gr = (const float4*)g;
    const float4* br = (const float4*)b;
    half2* yr = (half2*)(y + (size_t)warp * C_);
    #pragma unroll
    for (int i = 0; i < 4; i++) {
        float4 gg = gr[lane + 32 * i], bb = br[lane + 32 * i], vv = v[i], o4;
        o4.x = (vv.x - m) * rs * gg.x + bb.x;
        o4.y = (vv.y - m) * rs * gg.y + bb.y;
        o4.z = (vv.z - m) * rs * gg.z + bb.z;
        o4.w = (vv.w - m) * rs * gg.w + bb.w;
        yr[2 * (lane + 32 * i)]     = __floats2half2_rn(o4.x, o4.y);
        yr[2 * (lane + 32 * i) + 1] = __floats2half2_rn(o4.z, o4.w);
    }
}

// ---------------------------------------------------------------------------
// fp16 GEMM, fp32 accum: C[M,N] = A[M,K] @ B[N,K]^T, both K-major half.
// Block 128x128, BK=64 halves, 8 warps (4x2), warp tile 32x64, mma m16n8k16,
// ldmatrix.x4 fragment loads, cp.async double-buffered, pitch 72 halves (144B,
// ldmatrix- and STS.128-conflict-free).
// EPI: 1 = de-interleave QKV -> half q/k/v
//      2 = fp32 out = Res + acc
//      3 = half out = relu(acc + Bias)
//      4 = fp32 out = Res + acc + Bias
// ---------------------------------------------------------------------------
#define PITCH_H 72                     /* halves per smem row */
#define PITCH_B 144                    /* bytes per smem row */
#define SSTRIDE (128 * PITCH_B)        /* 18432 B per tile stage */
#define GEMM_SMEM (4 * SSTRIDE)        /* A0 A1 B0 B1 = 73728 B */

template <int EPI>
__device__ __forceinline__ void epi_store2(void* O0v, void* O1v, void* O2v,
                                           const float* Res, const float* Bias,
                                           int Ndim, int row, int col,
                                           float v0, float v1) {
    if (EPI == 1) {
        __half* O0 = (__half*)O0v; __half* O1 = (__half*)O1v; __half* O2 = (__half*)O2v;
        int gA = col, gB = col + 1;
        int cA = gA / 3, jA = gA - cA * 3;
        int cB = gB / 3, jB = gB - cB * 3;
        __half* pA = (jA == 0) ? O0 : ((jA == 1) ? O1 : O2);
        __half* pB = (jB == 0) ? O0 : ((jB == 1) ? O1 : O2);
        pA[(size_t)row * C_ + cA] = __float2half_rn(v0);
        pB[(size_t)row * C_ + cB] = __float2half_rn(v1);
    } else {
        size_t idx = (size_t)row * Ndim + col;
        if (EPI == 3) {
            v0 = fmaxf(v0 + Bias[col], 0.f);
            v1 = fmaxf(v1 + Bias[col + 1], 0.f);
            *(half2*)((__half*)O0v + idx) = __floats2half2_rn(v0, v1);
        } else {
            float* O0 = (float*)O0v;
            float2 rr = *(const float2*)(Res + idx);
            if (EPI == 2) { v0 += rr.x; v1 += rr.y; }
            else          { v0 += rr.x + Bias[col]; v1 += rr.y + Bias[col + 1]; }
            *(float2*)(O0 + idx) = make_float2(v0, v1);
        }
    }
}

__device__ __forceinline__ void load_tile64(uint32_t dstbase, const __half* src,
                                            int rowBase, int kHalf, int Kd, int tid) {
    // 128 rows x 128 B = 1024 16B chunks; 256 threads -> 4 iters
    #pragma unroll
    for (int i = 0; i < 4; i++) {
        int ch  = i * 256 + tid;
        int row = ch >> 3;
        int cb  = ch & 7;
        const __half* g = src + (size_t)(rowBase + row) * Kd + kHalf + cb * 8;
        CP_ASYNC16(dstbase + (uint32_t)(row * PITCH_B + cb * 16), g);
    }
}

template <int EPI>
__global__ void __launch_bounds__(256, 2) gemm_f16(
    const __half* __restrict__ A, const __half* __restrict__ Bm,
    void* O0, void* O1, void* O2,
    const float* __restrict__ Res, const float* __restrict__ Bias,
    int Ndim, int Kdim) {
    extern __shared__ __align__(16) uint8_t smem[];

    const int tid  = threadIdx.x;
    const int lane = tid & 31, warp = tid >> 5;
    const int wm = (warp & 3) * 32;
    const int wn = (warp >> 2) * 64;
    const int r  = lane >> 2, tc = lane & 3;
    const int mBase = blockIdx.y * 128;
    const int nBase = blockIdx.x * 128;

    const uint32_t sbase = smem_u32(smem);
    const uint32_t aBase = sbase;
    const uint32_t bBase = sbase + 2 * SSTRIDE;

    // per-lane ldmatrix address offsets (bytes)
    const uint32_t aOff = (uint32_t)((wm + (lane & 15)) * PITCH_B + (lane >> 4) * 16);
    const uint32_t bOff = (uint32_t)((wn + ((lane >> 4) & 1) * 8 + (lane & 7)) * PITCH_B
                                     + ((lane >> 3) & 1) * 16);

    float acc[2][8][4];
    #pragma unroll
    for (int i = 0; i < 2; i++)
        #pragma unroll
        for (int j = 0; j < 8; j++)
            #pragma unroll
            for (int q = 0; q < 4; q++) acc[i][j][q] = 0.f;

    const int nkt = Kdim >> 6;   // BK = 64 halves

    load_tile64(aBase, A,  mBase, 0, Kdim, tid);
    load_tile64(bBase, Bm, nBase, 0, Kdim, tid);
    CP_COMMIT;

    for (int kt = 0; kt < nkt; kt++) {
        const int cur = kt & 1;
        if (kt + 1 < nkt) {
            const int nxt = cur ^ 1;
            load_tile64(aBase + nxt * SSTRIDE, A,  mBase, (kt + 1) << 6, Kdim, tid);
            load_tile64(bBase + nxt * SSTRIDE, Bm, nBase, (kt + 1) << 6, Kdim, tid);
        }
        CP_COMMIT;
        CP_WAIT1;
        __syncthreads();

        const uint32_t aS = aBase + cur * SSTRIDE + aOff;
        const uint32_t bS = bBase + cur * SSTRIDE + bOff;
        #pragma unroll
        for (int ks = 0; ks < 4; ks++) {
            uint32_t af0[4], af1[4];
            LDSM4(af0[0], af0[1], af0[2], af0[3], aS + ks * 32);
            LDSM4(af1[0], af1[1], af1[2], af1[3], aS + 16 * PITCH_B + ks * 32);
            #pragma unroll
            for (int ntp = 0; ntp < 4; ntp++) {
                uint32_t bf[4];
                LDSM4(bf[0], bf[1], bf[2], bf[3], bS + ntp * 16 * PITCH_B + ks * 32);
                MMA_F16(acc[0][2 * ntp],     af0[0], af0[1], af0[2], af0[3], bf[0], bf[1]);
                MMA_F16(acc[1][2 * ntp],     af1[0], af1[1], af1[2], af1[3], bf[0], bf[1]);
                MMA_F16(acc[0][2 * ntp + 1], af0[0], af0[1], af0[2], af0[3], bf[2], bf[3]);
                MMA_F16(acc[1][2 * ntp + 1], af1[0], af1[1], af1[2], af1[3], bf[2], bf[3]);
            }
        }
        __syncthreads();
    }

    #pragma unroll
    for (int mt = 0; mt < 2; mt++) {
        #pragma unroll
        for (int nt = 0; nt < 8; nt++) {
            int grow = mBase + wm + mt * 16 + r;
            int gcol = nBase + wn + nt * 8 + (tc << 1);
            epi_store2<EPI>(O0, O1, O2, Res, Bias, Ndim, grow,     gcol, acc[mt][nt][0], acc[mt][nt][1]);
            epi_store2<EPI>(O0, O1, O2, Res, Bias, Ndim, grow + 8, gcol, acc[mt][nt][2], acc[mt][nt][3]);
        }
    }
}

// ---------------------------------------------------------------------------
// Attention core: half q/k/v in, fp32 math, half ctx out.
// ---------------------------------------------------------------------------
__global__ void __launch_bounds__(512) attn_kernel(
    const __half* __restrict__ Q, const __half* __restrict__ K,
    const __half* __restrict__ V, __half* __restrict__ O, int L) {
    __shared__ float sp[16][192];
    const int warp = threadIdx.x >> 5, lane = threadIdx.x & 31;
    const int perS = L >> 4;
    const int s  = blockIdx.x / perS;
    const int ql = (blockIdx.x % perS) * 16 + warp;
    const size_t base = (size_t)s * L;
    const float scale = 0.044194173824159216f;   // 1/sqrt(512)

    float2 qf[8];
    const half2* qrow = (const half2*)(Q + (base + ql) * C_);
    #pragma unroll
    for (int i = 0; i < 8; i++) qf[i] = __half22float2(qrow[i * 32 + lane]);

    for (int k = 0; k < L; k++) {
        const half2* kr = (const half2*)(K + (base + k) * C_);
        float p = 0.f;
        #pragma unroll
        for (int i = 0; i < 8; i++) {
            float2 kf = __half22float2(kr[i * 32 + lane]);
            p += qf[i].x * kf.x + qf[i].y * kf.y;
        }
        p = warp_sum(p);
        if (lane == 0) sp[warp][k] = p * scale;
    }
    __syncwarp();

    float mx = -1e30f;
    for (int k = lane; k < L; k += 32) mx = fmaxf(mx, sp[warp][k]);
    mx = warp_max(mx);
    float sum = 0.f;
    for (int k = lane; k < L; k += 32) {
        float e = __expf(sp[warp][k] - mx);
        sp[warp][k] = e;
        sum += e;
    }
    sum = warp_sum(sum);
    float inv = 1.f / sum;
    for (int k = lane; k < L; k += 32) sp[warp][k] *= inv;
    __syncwarp();

    float2 accv[8];
    #pragma unroll
    for (int i = 0; i < 8; i++) accv[i] = make_float2(0.f, 0.f);
    for (int k = 0; k < L; k++) {
        float w = sp[warp][k];
        const half2* vr = (const half2*)(V + (base + k) * C_);
        #pragma unroll
        for (int i = 0; i < 8; i++) {
            float2 vf = __half22float2(vr[i * 32 + lane]);
            accv[i].x += w * vf.x;
            accv[i].y += w * vf.y;
        }
    }
    half2* orow = (half2*)(O + (base + ql) * C_);
    #pragma unroll
    for (int i = 0; i < 8; i++) orow[i * 32 + lane] = __floats2half2_rn(accv[i].x, accv[i].y);
}

// ---------------------------------------------------------------------------
// Host launcher
// ---------------------------------------------------------------------------
extern "C" void kernel_launch(void* const* d_in, const int* in_sizes, int n_in,
                              void* d_out, int out_size) {
    const float* x      = (const float*)d_in[0];
    const float* w_qkv1 = (const float*)d_in[1];
    const float* w_out1 = (const float*)d_in[2];
    const float* w_qkv2 = (const float*)d_in[3];
    const float* w_out2 = (const float*)d_in[4];
    const float* g1v    = (const float*)d_in[5];
    const float* b1v    = (const float*)d_in[6];
    const float* g2v    = (const float*)d_in[7];
    const float* b2v    = (const float*)d_in[8];
    const float* g3v    = (const float*)d_in[9];
    const float* b3v    = (const float*)d_in[10];
    const float* w_fc1  = (const float*)d_in[11];
    const float* b_fc1  = (const float*)d_in[12];
    const float* w_fc2  = (const float*)d_in[13];
    const float* b_fc2  = (const float*)d_in[14];
    float* out = (float*)d_out;

    static float *bufA = nullptr, *bufB;
    static __half *lnh, *hh, *wq1h, *wo1h, *wq2h, *wo2h, *wf1h, *wf2h;
    if (!bufA) {
        cudaGetSymbolAddress((void**)&bufA, g_bufA);
        cudaGetSymbolAddress((void**)&bufB, g_bufB);
        cudaGetSymbolAddress((void**)&lnh,  g_lnh);
        cudaGetSymbolAddress((void**)&hh,   g_hh);
        cudaGetSymbolAddress((void**)&wq1h, g_wq1h);
        cudaGetSymbolAddress((void**)&wo1h, g_wo1h);
        cudaGetSymbolAddress((void**)&wq2h, g_wq2h);
        cudaGetSymbolAddress((void**)&wo2h, g_wo2h);
        cudaGetSymbolAddress((void**)&wf1h, g_wf1h);
        cudaGetSymbolAddress((void**)&wf2h, g_wf2h);
        cudaFuncSetAttribute(gemm_f16<1>, cudaFuncAttributeMaxDynamicSharedMemorySize, GEMM_SMEM);
        cudaFuncSetAttribute(gemm_f16<2>, cudaFuncAttributeMaxDynamicSharedMemorySize, GEMM_SMEM);
        cudaFuncSetAttribute(gemm_f16<3>, cudaFuncAttributeMaxDynamicSharedMemorySize, GEMM_SMEM);
        cudaFuncSetAttribute(gemm_f16<4>, cudaFuncAttributeMaxDynamicSharedMemorySize, GEMM_SMEM);
    }
    __half* qb   = hh;
    __half* kb   = hh + (size_t)NTOK * C_;
    __half* vb   = hh + (size_t)2 * NTOK * C_;
    __half* ctxb = hh + (size_t)3 * NTOK * C_;

    f2h_kernel<<<(3 * C_ * C_ / 4 + 255) / 256, 256>>>(w_qkv1, wq1h, 3 * C_ * C_ / 4);
    f2h_kernel<<<(C_ * C_ / 4 + 255) / 256,     256>>>(w_out1, wo1h, C_ * C_ / 4);
    f2h_kernel<<<(3 * C_ * C_ / 4 + 255) / 256, 256>>>(w_qkv2, wq2h, 3 * C_ * C_ / 4);
    f2h_kernel<<<(C_ * C_ / 4 + 255) / 256,     256>>>(w_out2, wo2h, C_ * C_ / 4);
    f2h_kernel<<<(4 * C_ * C_ / 4 + 255) / 256, 256>>>(w_fc1,  wf1h, 4 * C_ * C_ / 4);
    f2h_kernel<<<(4 * C_ * C_ / 4 + 255) / 256, 256>>>(w_fc2,  wf2h, 4 * C_ * C_ / 4);

    dim3 tblk(32, 8);
    dim3 tgrid(W_ / 32, C_ / 32, B_ * H_);

    transpose_in_kernel<<<tgrid, tblk>>>(x, bufA);
    ln_kernel<<<NTOK / 8, 256>>>(bufA, g1v, b1v, lnh);

    gemm_f16<1><<<dim3(1536 / 128, NTOK / 128), 256, GEMM_SMEM>>>(
        lnh, wq1h, qb, kb, vb, nullptr, nullptr, 1536, 512);

    attn_kernel<<<1536 * (48 / 16), 512>>>(qb, kb, vb, ctxb, 48);

    gemm_f16<2><<<dim3(512 / 128, NTOK / 128), 256, GEMM_SMEM>>>(
        ctxb, wo1h, bufA, nullptr, nullptr, bufA, nullptr, 512, 512);

    permute_mid_kernel<<<NTOK, 128>>>(bufA, bufB);
    ln_kernel<<<NTOK / 8, 256>>>(bufB, g2v, b2v, lnh);

    gemm_f16<1><<<dim3(1536 / 128, NTOK / 128), 256, GEMM_SMEM>>>(
        lnh, wq2h, qb, kb, vb, nullptr, nullptr, 1536, 512);

    attn_kernel<<<384 * (192 / 16), 512>>>(qb, kb, vb, ctxb, 192);

    gemm_f16<2><<<dim3(512 / 128, NTOK / 128), 256, GEMM_SMEM>>>(
        ctxb, wo2h, bufB, nullptr, nullptr, bufB, nullptr, 512, 512);

    ln_kernel<<<NTOK / 8, 256>>>(bufB, g3v, b3v, lnh);

    gemm_f16<3><<<dim3(2048 / 128, NTOK / 128), 256, GEMM_SMEM>>>(
        lnh, wf1h, hh, nullptr, nullptr, nullptr, b_fc1, 2048, 512);

    gemm_f16<4><<<dim3(512 / 128, NTOK / 128), 256, GEMM_SMEM>>>(
        hh, wf2h, bufB, nullptr, nullptr, bufB, b_fc2, 512, 2048);

    transpose_out_kernel<<<tgrid, tblk>>>(bufB, out);
}